// round 17
// baseline (speedup 1.0000x reference)
#include <cuda_runtime.h>
#include <cuda_bf16.h>
#include <cstdint>

// Problem constants
#define B    2
#define N    512
#define MV   512
#define DIN  256
#define H    16
#define DOUT 128
#define LN_EPS 1e-5f

__device__ float g_proj[B * N * 2 * H];            // 128 KB
__device__ float g_T[B * MV * H * DOUT];           // 8 MB

#define FMA_F32X2(d_, a_, b_, c_) \
    asm("fma.rn.f32x2 %0, %1, %2, %3;" : "=l"(d_) : "l"(a_), "l"(b_), "l"(c_))

#define DUP_F32X2(d_, f_) \
    asm("mov.b64 %0, {%1, %1};" : "=l"(d_) : "f"(f_))

#define STCS_V2U64(p_, x_, y_) \
    asm volatile("st.global.cs.v2.u64 [%0], {%1, %2};" \
                 :: "l"(p_), "l"(x_), "l"(y_) : "memory")

// ---------------------------------------------------------------------------
// kpre: fused LN + proj + T.  Grid 128 x 256 thr.
// CTA = (rg = blk>>1 : rows rg*16..+15) x (ph = blk&1 : p = ph*8..+7).
// smem: Wsl[128 pql][129] (transposed W_out slice, 66 KB)
//       Wins[256][32] (32 KB), xs[16][256] (16 KB), bqs[16][16]
// proj is computed by BOTH ph CTAs (identical values) — write is benign.
// ---------------------------------------------------------------------------
#define KP_WSTRIDE 129
#define KP_WSL_FLOATS (128 * KP_WSTRIDE)               // 16512
#define KP_WIN_FLOATS (DIN * 32)                       // 8192
#define KP_XS_FLOATS  (16 * DIN)                       // 4096
#define KP_BQ_FLOATS  (16 * 16)                        // 256
#define KP_SMEM_BYTES ((KP_WSL_FLOATS + KP_WIN_FLOATS + KP_XS_FLOATS + KP_BQ_FLOATS) * 4)

__global__ __launch_bounds__(256) void kpre(
    const float* __restrict__ feats, const float* __restrict__ gamma,
    const float* __restrict__ beta,  const float* __restrict__ W_in,
    const float* __restrict__ b_in,  const float* __restrict__ W_out,
    float* __restrict__ proj,        float* __restrict__ T)
{
    extern __shared__ float sm[];
    float* Wsl  = sm;
    float* Wins = sm + KP_WSL_FLOATS;
    float* xs   = sm + KP_WSL_FLOATS + KP_WIN_FLOATS;      // [16][256]
    float* bqs  = sm + KP_WSL_FLOATS + KP_WIN_FLOATS + KP_XS_FLOATS;

    int t    = threadIdx.x;
    int rg   = blockIdx.x >> 1;            // rows rg*16 .. +15
    int ph   = blockIdx.x & 1;             // p = ph*8 .. +7
    int w    = t >> 5;
    int lane = t & 31;

    // ---- stage Wsl = transposed ph-slice of W_out (k2-proven pattern) ----
    {
        const float4* W4 = (const float4*)W_out;       // [128 d][64 pq4]
        #pragma unroll
        for (int it = 0; it < 16; it++) {
            int idx = t + it * 256;                    // 0..4095
            int dd  = idx >> 5;                        // 0..127
            int c4  = idx & 31;                        // 0..31
            float4 v = W4[dd * 64 + ph * 32 + c4];
            int pql = c4 * 4;
            Wsl[(pql + 0) * KP_WSTRIDE + dd] = v.x;
            Wsl[(pql + 1) * KP_WSTRIDE + dd] = v.y;
            Wsl[(pql + 2) * KP_WSTRIDE + dd] = v.z;
            Wsl[(pql + 3) * KP_WSTRIDE + dd] = v.w;
        }
    }
    // ---- stage W_in (coalesced float4) ----
    #pragma unroll
    for (int it = 0; it < 8; it++) {
        int idx = t + it * 256;
        ((float4*)Wins)[idx] = ((const float4*)W_in)[idx];
    }

    // ---- Phase A: LN, warp w handles rows 2w and 2w+1 ----
    #pragma unroll
    for (int rr = 0; rr < 2; rr++) {
        int lr = 2 * w + rr;                           // local row 0..15
        int r  = rg * 16 + lr;                         // global row
        const float4* f4 = (const float4*)(feats + (size_t)r * DIN);
        float4 va = f4[lane * 2], vb = f4[lane * 2 + 1];
        float s  = va.x + va.y + va.z + va.w + vb.x + vb.y + vb.z + vb.w;
        float s2 = va.x*va.x + va.y*va.y + va.z*va.z + va.w*va.w
                 + vb.x*vb.x + vb.y*vb.y + vb.z*vb.z + vb.w*vb.w;
        #pragma unroll
        for (int o = 16; o; o >>= 1) {
            s  += __shfl_xor_sync(0xFFFFFFFFu, s,  o);
            s2 += __shfl_xor_sync(0xFFFFFFFFu, s2, o);
        }
        float mu  = s  * (1.f / DIN);
        float var = s2 * (1.f / DIN) - mu * mu;
        float rs  = rsqrtf(var + LN_EPS);

        const float4* g4 = (const float4*)gamma;
        const float4* b4 = (const float4*)beta;
        float4 ga = g4[lane * 2], gb = g4[lane * 2 + 1];
        float4 ba = b4[lane * 2], bb = b4[lane * 2 + 1];
        float* xrow = xs + lr * DIN + lane * 8;
        xrow[0] = (va.x - mu) * rs * ga.x + ba.x;
        xrow[1] = (va.y - mu) * rs * ga.y + ba.y;
        xrow[2] = (va.z - mu) * rs * ga.z + ba.z;
        xrow[3] = (va.w - mu) * rs * ga.w + ba.w;
        xrow[4] = (vb.x - mu) * rs * gb.x + bb.x;
        xrow[5] = (vb.y - mu) * rs * gb.y + bb.y;
        xrow[6] = (vb.z - mu) * rs * gb.z + bb.z;
        xrow[7] = (vb.w - mu) * rs * gb.w + bb.w;
    }
    __syncthreads();

    // ---- Phase B: proj for rows 2w, 2w+1, col lane.  Wins loads shared. ----
    {
        const float* x0 = xs + (2 * w)     * DIN;
        const float* x1 = xs + (2 * w + 1) * DIN;
        float p00 = 0.f, p01 = 0.f, p10 = 0.f, p11 = 0.f;
        #pragma unroll 16
        for (int i = 0; i < DIN; i += 2) {
            float w0 = Wins[(i)     * 32 + lane];
            float w1 = Wins[(i + 1) * 32 + lane];
            p00 = fmaf(x0[i],     w0, p00);
            p01 = fmaf(x0[i + 1], w1, p01);
            p10 = fmaf(x1[i],     w0, p10);
            p11 = fmaf(x1[i + 1], w1, p11);
        }
        float pv0 = b_in[lane] + (p00 + p01);
        float pv1 = b_in[lane] + (p10 + p11);
        int r0 = rg * 16 + 2 * w;
        proj[(size_t)r0 * 32 + lane]       = pv0;   // both ph write same vals
        proj[(size_t)(r0 + 1) * 32 + lane] = pv1;
        if (lane >= 16) {
            bqs[(2 * w)     * 16 + (lane - 16)] = pv0;
            bqs[(2 * w + 1) * 16 + (lane - 16)] = pv1;
        }
    }
    __syncthreads();

    // ---- Phase C (k2 verbatim): T for 16 rows x 8 p x 128 d ----
    {
        int d = t & 127;
        int h = t >> 7;                                // 0..1
        float wq[4][16];
        #pragma unroll
        for (int pi = 0; pi < 4; pi++) {
            int pl = h * 4 + pi;
            #pragma unroll
            for (int q = 0; q < 16; q++)
                wq[pi][q] = Wsl[(pl * 16 + q) * KP_WSTRIDE + d];
        }
        #pragma unroll
        for (int mm = 0; mm < 16; mm++) {
            float acc[4] = {0.f, 0.f, 0.f, 0.f};
            #pragma unroll
            for (int q = 0; q < 16; q++) {
                float bv = bqs[mm * 16 + q];
                acc[0] = fmaf(wq[0][q], bv, acc[0]);
                acc[1] = fmaf(wq[1][q], bv, acc[1]);
                acc[2] = fmaf(wq[2][q], bv, acc[2]);
                acc[3] = fmaf(wq[3][q], bv, acc[3]);
            }
            size_t bm = (size_t)(rg * 16 + mm);
            #pragma unroll
            for (int pi = 0; pi < 4; pi++) {
                int p = ph * 8 + h * 4 + pi;
                T[(bm * H + p) * DOUT + d] = acc[pi];
            }
        }
    }
}

// ---------------------------------------------------------------------------
// k_main (R7 verbatim, FROZEN): out = b_out + sum_p a * T
// Grid 1024, 256 thr, occ 2.  CTA = one (b,m); warp = 64 rows; T in regs.
// ---------------------------------------------------------------------------
__global__ __launch_bounds__(256, 2) void k_main(
    const float* __restrict__ proj, const float* __restrict__ Tg,
    const float* __restrict__ b_out, float* __restrict__ out)
{
    int b    = blockIdx.x >> 9;
    int m    = blockIdx.x & 511;
    int t    = threadIdx.x;
    int w    = t >> 5;              // warp -> rows w*64 .. w*64+63
    int lane = t & 31;              // chunk: d = lane*4 .. +3

    __shared__ __align__(16) float Ts[H * DOUT];   // 8 KB  [p][d]
    __shared__ __align__(16) float As[N * H];      // 32 KB [row][p]

    {
        const float4* Tsrc = (const float4*)(Tg + (size_t)(b * N + m) * (H * DOUT));
        float4* Td = (float4*)Ts;
        Td[t]       = Tsrc[t];
        Td[t + 256] = Tsrc[t + 256];
    }
    {
        const float4* psrc = (const float4*)(proj + (size_t)b * N * 32);
        float4* Ad = (float4*)As;
        #pragma unroll
        for (int it = 0; it < 8; it++) {
            int idx = t + it * 256;
            int row = idx >> 2;
            int q4  = idx & 3;
            Ad[idx] = psrc[row * 8 + q4];
        }
    }
    __syncthreads();

    unsigned long long Tp[H][2];
    {
        const ulonglong2* TU = (const ulonglong2*)Ts;
        #pragma unroll
        for (int p = 0; p < H; p++) {
            ulonglong2 q = TU[p * 32 + lane];
            Tp[p][0] = q.x; Tp[p][1] = q.y;
        }
    }

    unsigned long long bo0, bo1;
    {
        const unsigned long long* bo = (const unsigned long long*)b_out;
        bo0 = bo[2 * lane]; bo1 = bo[2 * lane + 1];
    }

    size_t rowstride = (size_t)MV * DOUT;
    float* obase = out + (((size_t)(b * N) + w * 64) * MV + m) * DOUT + lane * 4;

    #pragma unroll 1
    for (int jb = 0; jb < 64; jb += 4) {
        unsigned long long acc[4][2];
        #pragma unroll
        for (int j = 0; j < 4; j++) { acc[j][0] = bo0; acc[j][1] = bo1; }

        #pragma unroll
        for (int j = 0; j < 4; j++) {
            int row = w * 64 + jb + j;
            const float4* ar = (const float4*)(As + row * H);
            float4 A0 = ar[0], A1 = ar[1], A2 = ar[2], A3 = ar[3];
            float a16[16] = { A0.x,A0.y,A0.z,A0.w, A1.x,A1.y,A1.z,A1.w,
                              A2.x,A2.y,A2.z,A2.w, A3.x,A3.y,A3.z,A3.w };
            #pragma unroll
            for (int p = 0; p < H; p++) {
                unsigned long long ad;
                DUP_F32X2(ad, a16[p]);
                FMA_F32X2(acc[j][0], ad, Tp[p][0], acc[j][0]);
                FMA_F32X2(acc[j][1], ad, Tp[p][1], acc[j][1]);
            }
        }

        float* op = obase + (size_t)jb * rowstride;
        #pragma unroll
        for (int j = 0; j < 4; j++)
            STCS_V2U64(op + (size_t)j * rowstride, acc[j][0], acc[j][1]);
    }
}

// ---------------------------------------------------------------------------
extern "C" void kernel_launch(void* const* d_in, const int* in_sizes, int n_in,
                              void* d_out, int out_size)
{
    const float* feats  = (const float*)d_in[0];
    const float* gamma  = (const float*)d_in[1];
    const float* beta   = (const float*)d_in[2];
    const float* W_in   = (const float*)d_in[3];
    const float* b_in   = (const float*)d_in[4];
    const float* W_out  = (const float*)d_in[5];
    const float* b_out  = (const float*)d_in[6];
    float* out = (float*)d_out;

    float* proj; cudaGetSymbolAddress((void**)&proj, g_proj);
    float* T;    cudaGetSymbolAddress((void**)&T,    g_T);

    cudaFuncSetAttribute(kpre, cudaFuncAttributeMaxDynamicSharedMemorySize,
                         KP_SMEM_BYTES);

    kpre<<<128, 256, KP_SMEM_BYTES>>>(feats, gamma, beta, W_in, b_in, W_out,
                                      proj, T);
    k_main<<<B * MV, 256>>>(proj, T, b_out, out);
}